// round 12
// baseline (speedup 1.0000x reference)
#include <cuda_runtime.h>
#include <cstdint>

// Problem dims
#define G1 512
#define E_EDGES 16384
#define S1 8192
#define S2 8192
#define BT 128
#define MAXE 256   // per-t0 edge capacity (lambda=32; generous headroom)
#define DEPTH 4    // x cp.async pipeline depth

// -------- device scratch --------
__device__ float g_xperm[256 * S1];        //  8MB: x, tf32-rounded, K-cols permuted per 16-block
__device__ float g_vperm[E_EDGES * 256];   // 16MB: v, tf32-rounded, fragment-consumption order

// -------- fused preprocessing: xperm (blocks [0,512)) + vperm (blocks [512,4608)) --------
__global__ __launch_bounds__(256) void prep_kernel(const float* __restrict__ x,
                                                   const float* __restrict__ values) {
    if (blockIdx.x < 512) {
        // x: tf32 round + col' = (c%4)*4 + c/4 permute per 16-block
        const size_t blk = (size_t)blockIdx.x * 256 + threadIdx.x;
        const float4* src = reinterpret_cast<const float4*>(x + blk * 16);
        float4 a = __ldg(src + 0), b = __ldg(src + 1), c = __ldg(src + 2), d = __ldg(src + 3);
        float v[16] = {a.x,a.y,a.z,a.w, b.x,b.y,b.z,b.w, c.x,c.y,c.z,c.w, d.x,d.y,d.z,d.w};
        uint32_t t[16];
        #pragma unroll
        for (int i = 0; i < 16; i++)
            asm("cvt.rna.tf32.f32 %0, %1;" : "=r"(t[i]) : "f"(v[i]));
        float4* dst = reinterpret_cast<float4*>(g_xperm + blk * 16);
        #pragma unroll
        for (int g = 0; g < 4; g++)
            dst[g] = make_float4(__uint_as_float(t[g]),     __uint_as_float(t[g + 4]),
                                 __uint_as_float(t[g + 8]), __uint_as_float(t[g + 12]));
    } else {
        // v: tf32 round + fragment-consumption-order permute.
        // Consumer lane l (gid=l>>2, tig=l&3) reads vperm[e*256 + l*8 .. +8)
        const int t    = (blockIdx.x - 512) * 256 + threadIdx.x;   // 0 .. E*64-1
        const int e    = t >> 6;
        const int r    = t & 63;
        const int lane = r >> 1;
        const int half = r & 1;
        const int gid  = lane >> 2;
        const int tig  = lane & 3;
        const float* src = values + ((size_t)e << 8) + (tig << 4) + gid + (half << 3);
        uint32_t o[4];
        #pragma unroll
        for (int q = 0; q < 4; q++) {
            float f = __ldg(src + q * 64);
            asm("cvt.rna.tf32.f32 %0, %1;" : "=r"(o[q]) : "f"(f));
        }
        *reinterpret_cast<float4*>(g_vperm + ((size_t)e << 8) + (lane << 3) + (half << 2)) =
            make_float4(__uint_as_float(o[0]), __uint_as_float(o[1]),
                        __uint_as_float(o[2]), __uint_as_float(o[3]));
    }
}

// -------- helpers --------
__device__ __forceinline__ void cp16(uint32_t d, const void* g) {
    asm volatile("cp.async.cg.shared.global [%0], [%1], 16;" :: "r"(d), "l"(g));
}
__device__ __forceinline__ void cp_commit() { asm volatile("cp.async.commit_group;"); }
__device__ __forceinline__ void cp_wait3()  { asm volatile("cp.async.wait_group %0;" :: "n"(DEPTH - 1)); }

__device__ __forceinline__ void mma8(float* c,
                                     uint32_t a0, uint32_t a1, uint32_t a2, uint32_t a3,
                                     uint32_t b0, uint32_t b1) {
    asm volatile(
        "mma.sync.aligned.m16n8k8.row.col.f32.tf32.tf32.f32 "
        "{%0,%1,%2,%3}, {%4,%5,%6,%7}, {%8,%9}, {%0,%1,%2,%3};"
        : "+f"(c[0]), "+f"(c[1]), "+f"(c[2]), "+f"(c[3])
        : "r"(a0), "r"(a1), "r"(a2), "r"(a3), "r"(b0), "r"(b1));
}

union F4U { float4 f; uint32_t u[4]; };

// -------- main tensor SpMM --------
// grid (512 t0, 2 batch halves), 128 threads = 4 warps; warp w owns batch rows 32w..32w+31.
// x: lane-private cp.async ring (DEPTH=4, no CTA barriers in loop).
// v: depth-2 register pipeline from pre-permuted g_vperm (2 LDG.128, no cvt).
__global__ __launch_bounds__(128) void spmm_mma(
    const float* __restrict__ bias,
    const int*   __restrict__ ei,
    float* __restrict__ out)
{
    // lane-private x staging: [warp][stage][lane][20] (stride-20 pad -> conflict-free LDS.128)
    __shared__ __align__(16) float xbuf[4][DEPTH][32][20];   // 40 KB
    __shared__ int s_list[MAXE];                              // packed: (t1 << 16) | e
    __shared__ int s_cnt;

    const int tid  = threadIdx.x;
    const int lane = tid & 31;
    const int wid  = tid >> 5;
    const int gid  = lane >> 2;
    const int tig  = lane & 3;
    const int t0    = blockIdx.x;
    const int bbase = blockIdx.y * BT;

    // ---- self-bucket: scan edge_index for matches on t0 ----
    if (tid == 0) s_cnt = 0;
    __syncthreads();
    {
        const int4* ei4 = reinterpret_cast<const int4*>(ei);
        #pragma unroll 4
        for (int i = tid; i < E_EDGES / 4; i += 128) {
            const int4 q = __ldg(&ei4[i]);
            const int base = i << 2;
            if (q.x == t0) { int p = atomicAdd(&s_cnt, 1); if (p < MAXE) s_list[p] = (__ldg(ei + E_EDGES + base    ) << 16) | (base    ); }
            if (q.y == t0) { int p = atomicAdd(&s_cnt, 1); if (p < MAXE) s_list[p] = (__ldg(ei + E_EDGES + base + 1) << 16) | (base + 1); }
            if (q.z == t0) { int p = atomicAdd(&s_cnt, 1); if (p < MAXE) s_list[p] = (__ldg(ei + E_EDGES + base + 2) << 16) | (base + 2); }
            if (q.w == t0) { int p = atomicAdd(&s_cnt, 1); if (p < MAXE) s_list[p] = (__ldg(ei + E_EDGES + base + 3) << 16) | (base + 3); }
        }
    }
    __syncthreads();
    int n = s_cnt;
    if (n > MAXE) n = MAXE;

    // this lane's A source rows: (bbase + 32*wid + gid) + {0, 8, 16, 24}
    const float* xrow = g_xperm + (size_t)(bbase + (wid << 5) + gid) * S1 + (tig << 2);

    float acc[2][2][4];
    #pragma unroll
    for (int a = 0; a < 2; a++)
        #pragma unroll
        for (int b = 0; b < 2; b++)
            #pragma unroll
            for (int q = 0; q < 4; q++) acc[a][b][q] = 0.0f;

    // lane's smem slot base (stage 0); stage stride = 32*20*4 = 2560 B
    const uint32_t xslot = (uint32_t)__cvta_generic_to_shared(&xbuf[wid][0][lane][0]);

    F4U vf[2][2];   // v register pipeline (pre-converted tf32 bits)

    // issue x for edge k into ring stage s (cp.async; always followed by a commit at call site)
    auto issue_x = [&](int k, int s) {
        if (k < n) {
            const int t1 = s_list[k] >> 16;
            const float* xp = xrow + t1 * 16;
            const uint32_t d = xslot + (uint32_t)s * 2560u;
            cp16(d,      xp);
            cp16(d + 16, xp +  8 * S1);
            cp16(d + 32, xp + 16 * S1);
            cp16(d + 48, xp + 24 * S1);
        }
    };
    auto issue_v = [&](int k, int s) {
        if (k < n) {
            const int e = s_list[k] & 0xFFFF;
            const float* vp = g_vperm + ((size_t)e << 8) + (lane << 3);
            vf[s][0].f = __ldg(reinterpret_cast<const float4*>(vp));
            vf[s][1].f = __ldg(reinterpret_cast<const float4*>(vp + 4));
        }
    };

    // ---- prologue: fill x ring, start v pipeline ----
    #pragma unroll
    for (int d = 0; d < DEPTH; d++) { issue_x(d, d); cp_commit(); }
    issue_v(0, 0);
    issue_v(1, 1);

    for (int k = 0; k < n; k++) {
        const int sx = k & (DEPTH - 1);
        const int sv = k & 1;

        cp_wait3();   // stage k's x data landed (DEPTH-1 groups may remain in flight)

        // consume fragments
        const float* xs = &xbuf[wid][sx][lane][0];
        F4U X0, X1, X2, X3;
        X0.f = *reinterpret_cast<const float4*>(xs);
        X1.f = *reinterpret_cast<const float4*>(xs + 4);
        X2.f = *reinterpret_cast<const float4*>(xs + 8);
        X3.f = *reinterpret_cast<const float4*>(xs + 12);
        F4U B0 = vf[sv][0], B1 = vf[sv][1];

        // refill pipelines (reads above are same-lane and already performed)
        issue_v(k + 2, sv);
        issue_x(k + DEPTH, sx);
        cp_commit();   // unconditional: keeps group counting aligned

        mma8(acc[0][0], X0.u[0], X1.u[0], X0.u[1], X1.u[1], B0.u[0], B0.u[1]);
        mma8(acc[0][0], X0.u[2], X1.u[2], X0.u[3], X1.u[3], B0.u[2], B0.u[3]);
        mma8(acc[0][1], X0.u[0], X1.u[0], X0.u[1], X1.u[1], B1.u[0], B1.u[1]);
        mma8(acc[0][1], X0.u[2], X1.u[2], X0.u[3], X1.u[3], B1.u[2], B1.u[3]);
        mma8(acc[1][0], X2.u[0], X3.u[0], X2.u[1], X3.u[1], B0.u[0], B0.u[1]);
        mma8(acc[1][0], X2.u[2], X3.u[2], X2.u[3], X3.u[3], B0.u[2], B0.u[3]);
        mma8(acc[1][1], X2.u[0], X3.u[0], X2.u[1], X3.u[1], B1.u[0], B1.u[1]);
        mma8(acc[1][1], X2.u[2], X3.u[2], X2.u[3], X3.u[3], B1.u[2], B1.u[3]);
    }

    // ---- epilogue: bias + float2 stores (n == 0 -> pure bias) ----
    #pragma unroll
    for (int t = 0; t < 2; t++) {
        const int row = bbase + (wid << 5) + (t << 4) + gid;
        #pragma unroll
        for (int nt = 0; nt < 2; nt++) {
            const int col = t0 * 16 + (nt << 3) + (tig << 1);
            const float2 bv = __ldg(reinterpret_cast<const float2*>(bias + col));
            float2 o0 = make_float2(acc[t][nt][0] + bv.x, acc[t][nt][1] + bv.y);
            float2 o1 = make_float2(acc[t][nt][2] + bv.x, acc[t][nt][3] + bv.y);
            *reinterpret_cast<float2*>(out + (size_t)row * S2 + col)       = o0;
            *reinterpret_cast<float2*>(out + (size_t)(row + 8) * S2 + col) = o1;
        }
    }
}

// -------- launch: exactly 2 kernels --------
extern "C" void kernel_launch(void* const* d_in, const int* in_sizes, int n_in,
                              void* d_out, int out_size) {
    const float* x      = (const float*)d_in[0];   // (256, 8192)
    const float* values = (const float*)d_in[1];   // (4194304,)
    const float* bias   = (const float*)d_in[2];   // (8192,)
    const int*   eidx   = (const int*)d_in[3];     // (2, 16384)
    float* out = (float*)d_out;                    // (256, 8192)

    prep_kernel<<<512 + (E_EDGES * 64) / 256, 256>>>(x, values);
    dim3 grid(G1, 2);
    spmm_mma<<<grid, 128>>>(bias, eidx, out);
}

// round 13
// speedup vs baseline: 1.6377x; 1.6377x over previous
#include <cuda_runtime.h>
#include <cstdint>

// Problem dims
#define G1 512
#define E_EDGES 16384
#define S1 8192
#define S2 8192
#define BT 128
#define MAXE 256   // per-t0 edge capacity (lambda=32; generous headroom)

// -------- device scratch --------
__device__ float g_xperm[256 * S1];        //  8MB: x, tf32-rounded, K-cols permuted per 16-block
__device__ float g_vperm[E_EDGES * 256];   // 16MB: v, tf32-rounded, fragment-consumption order

// -------- fused preprocessing: xperm (blocks [0,512)) + vperm (blocks [512,4608)) --------
__global__ __launch_bounds__(256) void prep_kernel(const float* __restrict__ x,
                                                   const float* __restrict__ values) {
    if (blockIdx.x < 512) {
        // x: tf32 round + col' = (c%4)*4 + c/4 permute per 16-block
        const size_t blk = (size_t)blockIdx.x * 256 + threadIdx.x;
        const float4* src = reinterpret_cast<const float4*>(x + blk * 16);
        float4 a = __ldg(src + 0), b = __ldg(src + 1), c = __ldg(src + 2), d = __ldg(src + 3);
        float v[16] = {a.x,a.y,a.z,a.w, b.x,b.y,b.z,b.w, c.x,c.y,c.z,c.w, d.x,d.y,d.z,d.w};
        uint32_t t[16];
        #pragma unroll
        for (int i = 0; i < 16; i++)
            asm("cvt.rna.tf32.f32 %0, %1;" : "=r"(t[i]) : "f"(v[i]));
        float4* dst = reinterpret_cast<float4*>(g_xperm + blk * 16);
        #pragma unroll
        for (int g = 0; g < 4; g++)
            dst[g] = make_float4(__uint_as_float(t[g]),     __uint_as_float(t[g + 4]),
                                 __uint_as_float(t[g + 8]), __uint_as_float(t[g + 12]));
    } else {
        // v: tf32 round + fragment-consumption-order permute.
        // Consumer lane l (gid=l>>2, tig=l&3) reads vperm[e*256 + l*8 .. +8) =
        //   tf32(v[e*256 + (tig*16+gid) + h*8 + q*64]), h in {0,1}, q in {0..3}
        const int t    = (blockIdx.x - 512) * 256 + threadIdx.x;   // 0 .. E*64-1
        const int e    = t >> 6;
        const int r    = t & 63;
        const int lane = r >> 1;
        const int half = r & 1;
        const int gid  = lane >> 2;
        const int tig  = lane & 3;
        const float* src = values + ((size_t)e << 8) + (tig << 4) + gid + (half << 3);
        uint32_t o[4];
        #pragma unroll
        for (int q = 0; q < 4; q++) {
            float f = __ldg(src + q * 64);
            asm("cvt.rna.tf32.f32 %0, %1;" : "=r"(o[q]) : "f"(f));
        }
        *reinterpret_cast<float4*>(g_vperm + ((size_t)e << 8) + (lane << 3) + (half << 2)) =
            make_float4(__uint_as_float(o[0]), __uint_as_float(o[1]),
                        __uint_as_float(o[2]), __uint_as_float(o[3]));
    }
}

// -------- helpers --------
__device__ __forceinline__ void mma8(float* c,
                                     uint32_t a0, uint32_t a1, uint32_t a2, uint32_t a3,
                                     uint32_t b0, uint32_t b1) {
    asm volatile(
        "mma.sync.aligned.m16n8k8.row.col.f32.tf32.tf32.f32 "
        "{%0,%1,%2,%3}, {%4,%5,%6,%7}, {%8,%9}, {%0,%1,%2,%3};"
        : "+f"(c[0]), "+f"(c[1]), "+f"(c[2]), "+f"(c[3])
        : "r"(a0), "r"(a1), "r"(a2), "r"(a3), "r"(b0), "r"(b1));
}

union F4U { float4 f; uint32_t u[4]; };

// -------- main tensor SpMM: self-bucketing + warp-autonomous register pipeline --------
// grid (512 t0, 2 batch halves), 128 threads = 4 warps; warp w owns batch rows 32w..32w+31.
// Per lane per edge: 4x LDG.128 (A, permuted x) + 2x LDG.128 (B, pre-permuted tf32 v).
__global__ __launch_bounds__(128) void spmm_mma(
    const float* __restrict__ bias,
    const int*   __restrict__ ei,
    float* __restrict__ out)
{
    __shared__ int s_list[MAXE];   // packed: (t1 << 16) | e
    __shared__ int s_cnt;

    const int tid  = threadIdx.x;
    const int lane = tid & 31;
    const int wid  = tid >> 5;
    const int gid  = lane >> 2;
    const int tig  = lane & 3;
    const int t0    = blockIdx.x;
    const int bbase = blockIdx.y * BT;

    // ---- self-bucket: scan edge_index for matches on t0 ----
    if (tid == 0) s_cnt = 0;
    __syncthreads();
    {
        const int4* ei4 = reinterpret_cast<const int4*>(ei);
        #pragma unroll 4
        for (int i = tid; i < E_EDGES / 4; i += 128) {
            const int4 q = __ldg(&ei4[i]);
            const int base = i << 2;
            if (q.x == t0) { int p = atomicAdd(&s_cnt, 1); if (p < MAXE) s_list[p] = (__ldg(ei + E_EDGES + base    ) << 16) | (base    ); }
            if (q.y == t0) { int p = atomicAdd(&s_cnt, 1); if (p < MAXE) s_list[p] = (__ldg(ei + E_EDGES + base + 1) << 16) | (base + 1); }
            if (q.z == t0) { int p = atomicAdd(&s_cnt, 1); if (p < MAXE) s_list[p] = (__ldg(ei + E_EDGES + base + 2) << 16) | (base + 2); }
            if (q.w == t0) { int p = atomicAdd(&s_cnt, 1); if (p < MAXE) s_list[p] = (__ldg(ei + E_EDGES + base + 3) << 16) | (base + 3); }
        }
    }
    __syncthreads();
    int n = s_cnt;
    if (n > MAXE) n = MAXE;

    // this lane's A source rows: (bbase + 32*wid + gid) + {0, 8, 16, 24}
    const float* xrow = g_xperm + (size_t)(bbase + (wid << 5) + gid) * S1 + (tig << 2);

    float acc[2][2][4];
    #pragma unroll
    for (int a = 0; a < 2; a++)
        #pragma unroll
        for (int b = 0; b < 2; b++)
            #pragma unroll
            for (int q = 0; q < 4; q++) acc[a][b][q] = 0.0f;

    F4U xf[2][4];   // 2-slot pipeline of A fragments
    F4U vf[2][2];   // 2-slot pipeline of B fragments (pre-converted tf32 bits)

    auto issue = [&](int k, int s) {
        if (k < n) {
            const int p  = s_list[k];                 // LDS: fast edge decode
            const int e  = p & 0xFFFF;
            const int t1 = p >> 16;
            const float* xp = xrow + t1 * 16;
            xf[s][0].f = __ldg(reinterpret_cast<const float4*>(xp));
            xf[s][1].f = __ldg(reinterpret_cast<const float4*>(xp +  8 * S1));
            xf[s][2].f = __ldg(reinterpret_cast<const float4*>(xp + 16 * S1));
            xf[s][3].f = __ldg(reinterpret_cast<const float4*>(xp + 24 * S1));
            const float* vp = g_vperm + ((size_t)e << 8) + (lane << 3);
            vf[s][0].f = __ldg(reinterpret_cast<const float4*>(vp));
            vf[s][1].f = __ldg(reinterpret_cast<const float4*>(vp + 4));
        }
    };

    issue(0, 0);
    issue(1, 1);

    for (int k = 0; k < n; k++) {
        const int s = k & 1;

        F4U X0 = xf[s][0], X1 = xf[s][1], X2 = xf[s][2], X3 = xf[s][3];
        F4U B0 = vf[s][0], B1 = vf[s][1];

        issue(k + 2, s);

        mma8(acc[0][0], X0.u[0], X1.u[0], X0.u[1], X1.u[1], B0.u[0], B0.u[1]);
        mma8(acc[0][0], X0.u[2], X1.u[2], X0.u[3], X1.u[3], B0.u[2], B0.u[3]);
        mma8(acc[0][1], X0.u[0], X1.u[0], X0.u[1], X1.u[1], B1.u[0], B1.u[1]);
        mma8(acc[0][1], X0.u[2], X1.u[2], X0.u[3], X1.u[3], B1.u[2], B1.u[3]);
        mma8(acc[1][0], X2.u[0], X3.u[0], X2.u[1], X3.u[1], B0.u[0], B0.u[1]);
        mma8(acc[1][0], X2.u[2], X3.u[2], X2.u[3], X3.u[3], B0.u[2], B0.u[3]);
        mma8(acc[1][1], X2.u[0], X3.u[0], X2.u[1], X3.u[1], B1.u[0], B1.u[1]);
        mma8(acc[1][1], X2.u[2], X3.u[2], X2.u[3], X3.u[3], B1.u[2], B1.u[3]);
    }

    // ---- epilogue: bias + float2 stores (n == 0 -> pure bias) ----
    #pragma unroll
    for (int t = 0; t < 2; t++) {
        const int row = bbase + (wid << 5) + (t << 4) + gid;
        #pragma unroll
        for (int nt = 0; nt < 2; nt++) {
            const int col = t0 * 16 + (nt << 3) + (tig << 1);
            const float2 bv = __ldg(reinterpret_cast<const float2*>(bias + col));
            float2 o0 = make_float2(acc[t][nt][0] + bv.x, acc[t][nt][1] + bv.y);
            float2 o1 = make_float2(acc[t][nt][2] + bv.x, acc[t][nt][3] + bv.y);
            *reinterpret_cast<float2*>(out + (size_t)row * S2 + col)       = o0;
            *reinterpret_cast<float2*>(out + (size_t)(row + 8) * S2 + col) = o1;
        }
    }
}

// -------- launch: exactly 2 kernels --------
extern "C" void kernel_launch(void* const* d_in, const int* in_sizes, int n_in,
                              void* d_out, int out_size) {
    const float* x      = (const float*)d_in[0];   // (256, 8192)
    const float* values = (const float*)d_in[1];   // (4194304,)
    const float* bias   = (const float*)d_in[2];   // (8192,)
    const int*   eidx   = (const int*)d_in[3];     // (2, 16384)
    float* out = (float*)d_out;                    // (256, 8192)

    prep_kernel<<<512 + (E_EDGES * 64) / 256, 256>>>(x, values);
    dim3 grid(G1, 2);
    spmm_mma<<<grid, 128>>>(bias, eidx, out);
}